// round 1
// baseline (speedup 1.0000x reference)
#include <cuda_runtime.h>

#define HH 60
#define WW 60
#define DDZ 36
#define NP 2048
#define NC 13
#define GRID_SZ 0.08f

#define TX 8
#define TY 8
#define TZ 4
#define TPB (TX*TY*TZ)   // 256

// Per-Gaussian precomputed scratch (device globals: no allocation allowed)
__device__ float g_ixx[NP], g_iyy[NP], g_izz[NP], g_ixy[NP], g_iyz[NP], g_ixz[NP];
__device__ float g_mx[NP],  g_my[NP],  g_mz[NP],  g_op[NP];
__device__ int   g_bx[NP],  g_by[NP],  g_bz[NP],  g_r[NP];

__global__ void precompute_kernel(const float* __restrict__ means3D,
                                  const float* __restrict__ opac,
                                  const float* __restrict__ scales,
                                  const float* __restrict__ cov3D,
                                  const float* __restrict__ origin)
{
    int g = blockIdx.x * blockDim.x + threadIdx.x;
    if (g >= NP) return;

    // packed = cov.reshape(-1,9)[[0,4,8,1,5,2]] = (xx,yy,zz,xy,yz,xz)
    const float* cv = cov3D + g * 9;
    float a = cv[0], b = cv[4], c = cv[8];
    float d = cv[1], e = cv[5], f = cv[2];
    float det = a * (b * c - e * e) - d * (d * c - e * f) + f * (d * e - b * f);
    g_ixx[g] = (b * c - e * e) / det;
    g_iyy[g] = (a * c - f * f) / det;
    g_izz[g] = (a * b - d * d) / det;
    g_ixy[g] = (e * f - d * c) / det;
    g_iyz[g] = (d * f - a * e) / det;
    g_ixz[g] = (d * e - b * f) / det;

    float ox = origin[0], oy = origin[1], oz = origin[2];
    float mx = means3D[g * 3 + 0];
    float my = means3D[g * 3 + 1];
    float mz = means3D[g * 3 + 2];
    g_mx[g] = mx; g_my[g] = my; g_mz[g] = mz;
    // truncation toward zero matches jnp .astype(int32)
    g_bx[g] = (int)((mx - ox) / GRID_SZ);
    g_by[g] = (int)((my - oy) / GRID_SZ);
    g_bz[g] = (int)((mz - oz) / GRID_SZ);

    float s = fmaxf(scales[g * 3 + 0], fmaxf(scales[g * 3 + 1], scales[g * 3 + 2]));
    g_r[g] = (int)ceilf(s * 3.0f / GRID_SZ);

    g_op[g] = opac[g];
}

__global__ __launch_bounds__(TPB)
void aggregate_kernel(const float* __restrict__ pts,
                      const float* __restrict__ sem,
                      const float* __restrict__ origin,
                      float* __restrict__ out)
{
    __shared__ int   s_cnt;
    __shared__ short s_list[NP];

    const int t = threadIdx.x;
    if (t == 0) s_cnt = 0;
    __syncthreads();

    const int tlo_x = blockIdx.x * TX;
    const int tlo_y = blockIdx.y * TY;
    const int tlo_z = blockIdx.z * TZ;
    const int thi_x = min(tlo_x + TX - 1, HH - 1);
    const int thi_y = min(tlo_y + TY - 1, WW - 1);
    const int thi_z = min(tlo_z + TZ - 1, DDZ - 1);

    // Cooperative coarse cull: Gaussian box vs tile bounds
    for (int g = t; g < NP; g += TPB) {
        int r  = g_r[g];
        int bx = g_bx[g], by = g_by[g], bz = g_bz[g];
        bool hit = (bx - r <= thi_x) && (bx + r >= tlo_x)
                && (by - r <= thi_y) && (by + r >= tlo_y)
                && (bz - r <= thi_z) && (bz + r >= tlo_z);
        if (hit) {
            int pos = atomicAdd(&s_cnt, 1);
            s_list[pos] = (short)g;
        }
    }
    __syncthreads();
    const int nlist = s_cnt;

    // Thread -> voxel: z fastest within the lane index (store locality)
    const int tz = t & (TZ - 1);
    const int ty = (t >> 2) & (TY - 1);
    const int tx = t >> 5;
    const int x = tlo_x + tx;
    const int y = tlo_y + ty;
    const int z = tlo_z + tz;
    const bool valid = (x < HH) && (y < WW);

    const int pidx = (x * WW + y) * DDZ + z;

    float px = 0.f, py = 0.f, pz = 0.f;
    int pix = -100000, piy = -100000, piz = -100000;
    if (valid) {
        px = pts[pidx * 3 + 0];
        py = pts[pidx * 3 + 1];
        pz = pts[pidx * 3 + 2];
        float ox = origin[0], oy = origin[1], oz = origin[2];
        pix = (int)((px - ox) / GRID_SZ);
        piy = (int)((py - oy) / GRID_SZ);
        piz = (int)((pz - oz) / GRID_SZ);
    }

    float acc[NC];
#pragma unroll
    for (int c = 0; c < NC; c++) acc[c] = 0.0f;

    for (int i = 0; i < nlist; i++) {
        const int g = s_list[i];
        const int r = g_r[g];
        bool inbox = (abs(pix - g_bx[g]) <= r)
                  && (abs(piy - g_by[g]) <= r)
                  && (abs(piz - g_bz[g]) <= r);
        // (invalid lanes have pix=-1e5 -> never inbox)
        if (__any_sync(0xffffffffu, inbox)) {
            float dx = px - g_mx[g];
            float dy = py - g_my[g];
            float dz = pz - g_mz[g];
            float quad = g_ixx[g] * dx * dx + g_iyy[g] * dy * dy + g_izz[g] * dz * dz
                       + 2.0f * (g_ixy[g] * dx * dy + g_iyz[g] * dy * dz + g_ixz[g] * dx * dz);
            float w = inbox ? (g_op[g] * __expf(-0.5f * quad)) : 0.0f;
            const float* sg = sem + g * NC;
#pragma unroll
            for (int c = 0; c < NC; c++)
                acc[c] = fmaf(w, __ldg(sg + c), acc[c]);
        }
    }

    if (valid) {
#pragma unroll
        for (int c = 0; c < NC; c++)
            out[pidx * NC + c] = acc[c];
    }
}

extern "C" void kernel_launch(void* const* d_in, const int* in_sizes, int n_in,
                              void* d_out, int out_size)
{
    const float* pts      = (const float*)d_in[0];   // [1,129600,3]
    const float* means3D  = (const float*)d_in[1];   // [1,2048,3]
    const float* opac     = (const float*)d_in[2];   // [1,2048]
    const float* sem      = (const float*)d_in[3];   // [1,2048,13]
    const float* scales   = (const float*)d_in[4];   // [1,2048,3]
    const float* cov3D    = (const float*)d_in[5];   // [1,2048,3,3]
    const float* origin   = (const float*)d_in[6];   // [3]
    float* out = (float*)d_out;                      // [129600,13] f32

    precompute_kernel<<<(NP + 255) / 256, 256>>>(means3D, opac, scales, cov3D, origin);

    dim3 grid((HH + TX - 1) / TX, (WW + TY - 1) / TY, (DDZ + TZ - 1) / TZ); // 8,8,9
    aggregate_kernel<<<grid, TPB>>>(pts, sem, origin, out);
}

// round 2
// speedup vs baseline: 2.2392x; 2.2392x over previous
#include <cuda_runtime.h>

#define HH 60
#define WW 60
#define DDZ 36
#define NP 2048
#define NC 13
#define GRID_SZ 0.08f

#define TX 8
#define TY 8
#define TZ 4
#define TPB (TX*TY*TZ)   // 256
#define BATCH TPB        // survivors staged per batch

// Per-Gaussian precomputed scratch (device globals: no allocation allowed)
__device__ int4   g_box[NP];        // bx, by, bz, r
__device__ float4 g_q0[NP];         // -0.5*ixx, -0.5*iyy, -0.5*izz, (pad)
__device__ float4 g_q1[NP];         // -ixy, -iyz, -ixz, mx
__device__ float2 g_q2[NP];         // my, mz
__device__ float  g_semop[NP][NC];  // opacity * semantics

__global__ void precompute_kernel(const float* __restrict__ means3D,
                                  const float* __restrict__ opac,
                                  const float* __restrict__ semantics,
                                  const float* __restrict__ scales,
                                  const float* __restrict__ cov3D,
                                  const float* __restrict__ origin)
{
    int g = blockIdx.x * blockDim.x + threadIdx.x;
    if (g >= NP) return;

    // packed = cov.reshape(-1,9)[[0,4,8,1,5,2]] = (xx,yy,zz,xy,yz,xz)
    const float* cv = cov3D + g * 9;
    float a = cv[0], b = cv[4], c = cv[8];
    float d = cv[1], e = cv[5], f = cv[2];
    float det = a * (b * c - e * e) - d * (d * c - e * f) + f * (d * e - b * f);
    float ixx = (b * c - e * e) / det;
    float iyy = (a * c - f * f) / det;
    float izz = (a * b - d * d) / det;
    float ixy = (e * f - d * c) / det;
    float iyz = (d * f - a * e) / det;
    float ixz = (d * e - b * f) / det;

    float ox = origin[0], oy = origin[1], oz = origin[2];
    float mx = means3D[g * 3 + 0];
    float my = means3D[g * 3 + 1];
    float mz = means3D[g * 3 + 2];

    float s = fmaxf(scales[g * 3 + 0], fmaxf(scales[g * 3 + 1], scales[g * 3 + 2]));
    int r = (int)ceilf(s * 3.0f / GRID_SZ);

    // truncation toward zero matches jnp .astype(int32)
    g_box[g] = make_int4((int)((mx - ox) / GRID_SZ),
                         (int)((my - oy) / GRID_SZ),
                         (int)((mz - oz) / GRID_SZ), r);
    g_q0[g] = make_float4(-0.5f * ixx, -0.5f * iyy, -0.5f * izz, 0.0f);
    g_q1[g] = make_float4(-ixy, -iyz, -ixz, mx);
    g_q2[g] = make_float2(my, mz);

    float op = opac[g];
#pragma unroll
    for (int cc = 0; cc < NC; cc++)
        g_semop[g][cc] = op * semantics[g * NC + cc];
}

__global__ __launch_bounds__(TPB)
void aggregate_kernel(const float* __restrict__ pts,
                      const float* __restrict__ origin,
                      float* __restrict__ out)
{
    __shared__ int    s_cnt;
    __shared__ short  s_list[NP];
    __shared__ int4   s_box[BATCH];
    __shared__ float4 s_q0[BATCH];
    __shared__ float4 s_q1[BATCH];
    __shared__ float2 s_q2[BATCH];
    __shared__ float  s_sem[BATCH][NC];

    const int t = threadIdx.x;
    if (t == 0) s_cnt = 0;
    __syncthreads();

    const int tlo_x = blockIdx.x * TX;
    const int tlo_y = blockIdx.y * TY;
    const int tlo_z = blockIdx.z * TZ;
    const int thi_x = min(tlo_x + TX - 1, HH - 1);
    const int thi_y = min(tlo_y + TY - 1, WW - 1);
    const int thi_z = min(tlo_z + TZ - 1, DDZ - 1);

    // Cooperative coarse cull: Gaussian box vs tile bounds
    for (int g = t; g < NP; g += TPB) {
        int4 bx = g_box[g];
        bool hit = (bx.x - bx.w <= thi_x) && (bx.x + bx.w >= tlo_x)
                && (bx.y - bx.w <= thi_y) && (bx.y + bx.w >= tlo_y)
                && (bx.z - bx.w <= thi_z) && (bx.z + bx.w >= tlo_z);
        if (hit) {
            int pos = atomicAdd(&s_cnt, 1);
            s_list[pos] = (short)g;
        }
    }
    __syncthreads();
    const int nlist = s_cnt;

    // Thread -> voxel: z fastest within the lane index (store locality)
    const int tz = t & (TZ - 1);
    const int ty = (t >> 2) & (TY - 1);
    const int tx = t >> 5;
    const int x = tlo_x + tx;
    const int y = tlo_y + ty;
    const int z = tlo_z + tz;
    const bool valid = (x < HH) && (y < WW);

    const int pidx = (x * WW + y) * DDZ + z;

    float px = 0.f, py = 0.f, pz = 0.f;
    int pix = -100000, piy = -100000, piz = -100000;
    if (valid) {
        px = pts[pidx * 3 + 0];
        py = pts[pidx * 3 + 1];
        pz = pts[pidx * 3 + 2];
        float ox = origin[0], oy = origin[1], oz = origin[2];
        pix = (int)((px - ox) / GRID_SZ);
        piy = (int)((py - oy) / GRID_SZ);
        piz = (int)((pz - oz) / GRID_SZ);
    }

    float acc[NC];
#pragma unroll
    for (int c = 0; c < NC; c++) acc[c] = 0.0f;

    for (int base = 0; base < nlist; base += BATCH) {
        const int cnt = min(BATCH, nlist - base);

        // Stage this batch of survivors into SMEM (one thread per survivor)
        if (t < cnt) {
            int g = s_list[base + t];
            s_box[t] = g_box[g];
            s_q0[t]  = g_q0[g];
            s_q1[t]  = g_q1[g];
            s_q2[t]  = g_q2[g];
#pragma unroll
            for (int c = 0; c < NC; c++)
                s_sem[t][c] = g_semop[g][c];
        }
        __syncthreads();

#pragma unroll 2
        for (int i = 0; i < cnt; i++) {
            const int4 bx = s_box[i];
            bool inbox = (abs(pix - bx.x) <= bx.w)
                      && (abs(piy - bx.y) <= bx.w)
                      && (abs(piz - bx.z) <= bx.w);
            // invalid lanes have pix=-1e5 -> never inbox
            if (__any_sync(0xffffffffu, inbox)) {
                const float4 q1 = s_q1[i];
                const float2 q2 = s_q2[i];
                const float4 q0 = s_q0[i];
                float dx = px - q1.w;
                float dy = py - q2.x;
                float dz = pz - q2.y;
                float earg = q0.x * dx * dx + q0.y * dy * dy + q0.z * dz * dz
                           + q1.x * dx * dy + q1.y * dy * dz + q1.z * dx * dz;
                float w = inbox ? __expf(earg) : 0.0f;
#pragma unroll
                for (int c = 0; c < NC; c++)
                    acc[c] = fmaf(w, s_sem[i][c], acc[c]);
            }
        }
        __syncthreads();
    }

    if (valid) {
#pragma unroll
        for (int c = 0; c < NC; c++)
            out[pidx * NC + c] = acc[c];
    }
}

extern "C" void kernel_launch(void* const* d_in, const int* in_sizes, int n_in,
                              void* d_out, int out_size)
{
    const float* pts      = (const float*)d_in[0];   // [1,129600,3]
    const float* means3D  = (const float*)d_in[1];   // [1,2048,3]
    const float* opac     = (const float*)d_in[2];   // [1,2048]
    const float* sem      = (const float*)d_in[3];   // [1,2048,13]
    const float* scales   = (const float*)d_in[4];   // [1,2048,3]
    const float* cov3D    = (const float*)d_in[5];   // [1,2048,3,3]
    const float* origin   = (const float*)d_in[6];   // [3]
    float* out = (float*)d_out;                      // [129600,13] f32

    precompute_kernel<<<(NP + 255) / 256, 256>>>(means3D, opac, sem, scales, cov3D, origin);

    dim3 grid((HH + TX - 1) / TX, (WW + TY - 1) / TY, (DDZ + TZ - 1) / TZ); // 8,8,9
    aggregate_kernel<<<grid, TPB>>>(pts, origin, out);
}

// round 3
// speedup vs baseline: 2.2422x; 1.0014x over previous
#include <cuda_runtime.h>

#define HH 60
#define WW 60
#define DDZ 36
#define NP 2048
#define NC 13
#define GRID_SZ 0.08f

#define TX 4
#define TY 8
#define TZ 8          // tile z extent (each thread: z and z+4)
#define TZS 4         // z sub-positions per thread
#define TPB 128
#define BATCH 128

// Per-Gaussian precomputed scratch (device globals: no allocation allowed)
__device__ int4   g_box[NP];       // bx, by, bz, r
__device__ float4 g_q0[NP];        // -0.5*ixx, -0.5*iyy, -0.5*izz, pad
__device__ float4 g_q1[NP];        // -ixy, -iyz, -ixz, mx
__device__ float2 g_q2[NP];        // my, mz
__device__ float4 g_sem4[NP][4];   // opacity * semantics, padded 13 -> 16

__global__ void precompute_kernel(const float* __restrict__ means3D,
                                  const float* __restrict__ opac,
                                  const float* __restrict__ semantics,
                                  const float* __restrict__ scales,
                                  const float* __restrict__ cov3D,
                                  const float* __restrict__ origin)
{
    int g = blockIdx.x * blockDim.x + threadIdx.x;
    if (g >= NP) return;

    // packed = cov.reshape(-1,9)[[0,4,8,1,5,2]] = (xx,yy,zz,xy,yz,xz)
    const float* cv = cov3D + g * 9;
    float a = cv[0], b = cv[4], c = cv[8];
    float d = cv[1], e = cv[5], f = cv[2];
    float det = a * (b * c - e * e) - d * (d * c - e * f) + f * (d * e - b * f);
    float ixx = (b * c - e * e) / det;
    float iyy = (a * c - f * f) / det;
    float izz = (a * b - d * d) / det;
    float ixy = (e * f - d * c) / det;
    float iyz = (d * f - a * e) / det;
    float ixz = (d * e - b * f) / det;

    float ox = origin[0], oy = origin[1], oz = origin[2];
    float mx = means3D[g * 3 + 0];
    float my = means3D[g * 3 + 1];
    float mz = means3D[g * 3 + 2];

    float s = fmaxf(scales[g * 3 + 0], fmaxf(scales[g * 3 + 1], scales[g * 3 + 2]));
    int r = (int)ceilf(s * 3.0f / GRID_SZ);

    // truncation toward zero matches jnp .astype(int32)
    g_box[g] = make_int4((int)((mx - ox) / GRID_SZ),
                         (int)((my - oy) / GRID_SZ),
                         (int)((mz - oz) / GRID_SZ), r);
    g_q0[g] = make_float4(-0.5f * ixx, -0.5f * iyy, -0.5f * izz, 0.0f);
    g_q1[g] = make_float4(-ixy, -iyz, -ixz, mx);
    g_q2[g] = make_float2(my, mz);

    float op = opac[g];
    float sv[16];
#pragma unroll
    for (int cc = 0; cc < NC; cc++) sv[cc] = op * semantics[g * NC + cc];
#pragma unroll
    for (int cc = NC; cc < 16; cc++) sv[cc] = 0.0f;
#pragma unroll
    for (int q = 0; q < 4; q++)
        g_sem4[g][q] = make_float4(sv[q*4], sv[q*4+1], sv[q*4+2], sv[q*4+3]);
}

__global__ __launch_bounds__(TPB)
void aggregate_kernel(const float* __restrict__ pts,
                      const float* __restrict__ origin,
                      float* __restrict__ out)
{
    __shared__ int    s_cnt;
    __shared__ short  s_list[NP];
    __shared__ int4   s_box[BATCH];
    __shared__ float4 s_q0[BATCH];
    __shared__ float4 s_q1[BATCH];
    __shared__ float2 s_q2[BATCH];
    __shared__ float4 s_sem[BATCH][4];

    const int t = threadIdx.x;
    if (t == 0) s_cnt = 0;
    __syncthreads();

    const int tlo_x = blockIdx.x * TX;
    const int tlo_y = blockIdx.y * TY;
    const int tlo_z = blockIdx.z * TZ;
    const int thi_x = tlo_x + TX - 1;                 // x always in range (15*4=60)
    const int thi_y = min(tlo_y + TY - 1, WW - 1);
    const int thi_z = min(tlo_z + TZ - 1, DDZ - 1);

    // Cooperative coarse cull: Gaussian box vs tile bounds
    for (int g = t; g < NP; g += TPB) {
        int4 bx = g_box[g];
        bool hit = (bx.x - bx.w <= thi_x) && (bx.x + bx.w >= tlo_x)
                && (bx.y - bx.w <= thi_y) && (bx.y + bx.w >= tlo_y)
                && (bx.z - bx.w <= thi_z) && (bx.z + bx.w >= tlo_z);
        if (hit) {
            int pos = atomicAdd(&s_cnt, 1);
            s_list[pos] = (short)g;
        }
    }
    __syncthreads();
    const int nlist = s_cnt;

    // Thread -> voxel pair: tz fastest (z locality), then y, then x
    const int tz = t & (TZS - 1);
    const int ty = (t >> 2) & (TY - 1);
    const int tx = t >> 5;
    const int x  = tlo_x + tx;
    const int y  = tlo_y + ty;
    const int z0 = tlo_z + tz;           // always < 36 (tlo_z<=32, tz<=3)
    const int z1 = z0 + TZS;
    const bool valid0 = (y < WW);
    const bool valid1 = valid0 && (z1 < DDZ);

    const int pidx0 = (x * WW + y) * DDZ + z0;
    const int pidx1 = pidx0 + TZS;

    float px = 0.f, py = 0.f, pz0 = 0.f, pz1 = 0.f;
    int pix = -100000, piy = -100000, piz0 = -100000, piz1 = -100000;
    if (valid0) {
        px  = pts[pidx0 * 3 + 0];
        py  = pts[pidx0 * 3 + 1];
        pz0 = pts[pidx0 * 3 + 2];
        float ox = origin[0], oy = origin[1], oz = origin[2];
        pix  = (int)((px - ox) / GRID_SZ);
        piy  = (int)((py - oy) / GRID_SZ);
        piz0 = (int)((pz0 - oz) / GRID_SZ);
        if (valid1) {
            pz1  = pts[pidx1 * 3 + 2];
            piz1 = (int)((pz1 - origin[2]) / GRID_SZ);
        }
    }

    float acc0[NC], acc1[NC];
#pragma unroll
    for (int c = 0; c < NC; c++) { acc0[c] = 0.0f; acc1[c] = 0.0f; }

    for (int base = 0; base < nlist; base += BATCH) {
        const int cnt = min(BATCH, nlist - base);

        if (t < cnt) {
            int g = s_list[base + t];
            s_box[t] = g_box[g];
            s_q0[t]  = g_q0[g];
            s_q1[t]  = g_q1[g];
            s_q2[t]  = g_q2[g];
#pragma unroll
            for (int q = 0; q < 4; q++) s_sem[t][q] = g_sem4[g][q];
        }
        __syncthreads();

        for (int i = 0; i < cnt; i++) {
            const int4 bx = s_box[i];
            bool ibxy = (abs(pix - bx.x) <= bx.w) & (abs(piy - bx.y) <= bx.w);
            bool ib0 = ibxy & (abs(piz0 - bx.z) <= bx.w);
            bool ib1 = ibxy & (abs(piz1 - bx.z) <= bx.w);
            if (__any_sync(0xffffffffu, ib0 | ib1)) {
                const float4 q1 = s_q1[i];
                const float2 q2 = s_q2[i];
                const float4 q0 = s_q0[i];
                float dx  = px  - q1.w;
                float dy  = py  - q2.x;
                float dz0 = pz0 - q2.y;
                float dz1 = pz1 - q2.y;
                // shared xy part + shared cross helper
                float exy = fmaf(q0.x * dx, dx, fmaf(q0.y * dy, dy, q1.x * dx * dy));
                float h   = fmaf(q1.y, dy, q1.z * dx);
                float e0  = fmaf(fmaf(q0.z, dz0, h), dz0, exy);
                float e1  = fmaf(fmaf(q0.z, dz1, h), dz1, exy);
                float w0 = ib0 ? __expf(e0) : 0.0f;
                float w1 = ib1 ? __expf(e1) : 0.0f;
                const float4 sA = s_sem[i][0];
                const float4 sB = s_sem[i][1];
                const float4 sC = s_sem[i][2];
                const float4 sD = s_sem[i][3];
                acc0[0]  = fmaf(w0, sA.x, acc0[0]);   acc1[0]  = fmaf(w1, sA.x, acc1[0]);
                acc0[1]  = fmaf(w0, sA.y, acc0[1]);   acc1[1]  = fmaf(w1, sA.y, acc1[1]);
                acc0[2]  = fmaf(w0, sA.z, acc0[2]);   acc1[2]  = fmaf(w1, sA.z, acc1[2]);
                acc0[3]  = fmaf(w0, sA.w, acc0[3]);   acc1[3]  = fmaf(w1, sA.w, acc1[3]);
                acc0[4]  = fmaf(w0, sB.x, acc0[4]);   acc1[4]  = fmaf(w1, sB.x, acc1[4]);
                acc0[5]  = fmaf(w0, sB.y, acc0[5]);   acc1[5]  = fmaf(w1, sB.y, acc1[5]);
                acc0[6]  = fmaf(w0, sB.z, acc0[6]);   acc1[6]  = fmaf(w1, sB.z, acc1[6]);
                acc0[7]  = fmaf(w0, sB.w, acc0[7]);   acc1[7]  = fmaf(w1, sB.w, acc1[7]);
                acc0[8]  = fmaf(w0, sC.x, acc0[8]);   acc1[8]  = fmaf(w1, sC.x, acc1[8]);
                acc0[9]  = fmaf(w0, sC.y, acc0[9]);   acc1[9]  = fmaf(w1, sC.y, acc1[9]);
                acc0[10] = fmaf(w0, sC.z, acc0[10]);  acc1[10] = fmaf(w1, sC.z, acc1[10]);
                acc0[11] = fmaf(w0, sC.w, acc0[11]);  acc1[11] = fmaf(w1, sC.w, acc1[11]);
                acc0[12] = fmaf(w0, sD.x, acc0[12]);  acc1[12] = fmaf(w1, sD.x, acc1[12]);
            }
        }
        __syncthreads();
    }

    if (valid0) {
#pragma unroll
        for (int c = 0; c < NC; c++) out[pidx0 * NC + c] = acc0[c];
    }
    if (valid1) {
#pragma unroll
        for (int c = 0; c < NC; c++) out[pidx1 * NC + c] = acc1[c];
    }
}

extern "C" void kernel_launch(void* const* d_in, const int* in_sizes, int n_in,
                              void* d_out, int out_size)
{
    const float* pts      = (const float*)d_in[0];   // [1,129600,3]
    const float* means3D  = (const float*)d_in[1];   // [1,2048,3]
    const float* opac     = (const float*)d_in[2];   // [1,2048]
    const float* sem      = (const float*)d_in[3];   // [1,2048,13]
    const float* scales   = (const float*)d_in[4];   // [1,2048,3]
    const float* cov3D    = (const float*)d_in[5];   // [1,2048,3,3]
    const float* origin   = (const float*)d_in[6];   // [3]
    float* out = (float*)d_out;                      // [129600,13] f32

    precompute_kernel<<<(NP + 255) / 256, 256>>>(means3D, opac, sem, scales, cov3D, origin);

    dim3 grid(HH / TX, (WW + TY - 1) / TY, (DDZ + TZ - 1) / TZ); // 15, 8, 5
    aggregate_kernel<<<grid, TPB>>>(pts, origin, out);
}

// round 4
// speedup vs baseline: 2.6826x; 1.1964x over previous
#include <cuda_runtime.h>

#define HH 60
#define WW 60
#define DDZ 36
#define NP 2048
#define NC 13
#define GRID_SZ 0.08f

#define TX 4
#define TY 8
#define TZ 8          // tile z extent (each compute thread: z and z+4)
#define TZS 4
#define TPB 256       // 2 halves x 128 compute lanes
#define HALF 128
#define BATCH 256

// Per-Gaussian precomputed scratch (device globals: no allocation allowed)
__device__ int4   g_box[NP];       // bx, by, bz, r
__device__ float4 g_q0[NP];        // -0.5*ixx, -0.5*iyy, -0.5*izz, pad
__device__ float4 g_q1[NP];        // -ixy, -iyz, -ixz, mx
__device__ float2 g_q2[NP];        // my, mz
__device__ float4 g_sem4[NP][4];   // opacity * semantics, padded 13 -> 16

__global__ void precompute_kernel(const float* __restrict__ means3D,
                                  const float* __restrict__ opac,
                                  const float* __restrict__ semantics,
                                  const float* __restrict__ scales,
                                  const float* __restrict__ cov3D,
                                  const float* __restrict__ origin)
{
    int g = blockIdx.x * blockDim.x + threadIdx.x;
    if (g >= NP) return;

    const float* cv = cov3D + g * 9;
    float a = cv[0], b = cv[4], c = cv[8];
    float d = cv[1], e = cv[5], f = cv[2];
    float det = a * (b * c - e * e) - d * (d * c - e * f) + f * (d * e - b * f);
    float ixx = (b * c - e * e) / det;
    float iyy = (a * c - f * f) / det;
    float izz = (a * b - d * d) / det;
    float ixy = (e * f - d * c) / det;
    float iyz = (d * f - a * e) / det;
    float ixz = (d * e - b * f) / det;

    float ox = origin[0], oy = origin[1], oz = origin[2];
    float mx = means3D[g * 3 + 0];
    float my = means3D[g * 3 + 1];
    float mz = means3D[g * 3 + 2];

    float s = fmaxf(scales[g * 3 + 0], fmaxf(scales[g * 3 + 1], scales[g * 3 + 2]));
    int r = (int)ceilf(s * 3.0f / GRID_SZ);

    g_box[g] = make_int4((int)((mx - ox) / GRID_SZ),
                         (int)((my - oy) / GRID_SZ),
                         (int)((mz - oz) / GRID_SZ), r);
    g_q0[g] = make_float4(-0.5f * ixx, -0.5f * iyy, -0.5f * izz, 0.0f);
    g_q1[g] = make_float4(-ixy, -iyz, -ixz, mx);
    g_q2[g] = make_float2(my, mz);

    float op = opac[g];
    float sv[16];
#pragma unroll
    for (int cc = 0; cc < NC; cc++) sv[cc] = op * semantics[g * NC + cc];
#pragma unroll
    for (int cc = NC; cc < 16; cc++) sv[cc] = 0.0f;
#pragma unroll
    for (int q = 0; q < 4; q++)
        g_sem4[g][q] = make_float4(sv[q*4], sv[q*4+1], sv[q*4+2], sv[q*4+3]);
}

__global__ __launch_bounds__(TPB)
void aggregate_kernel(const float* __restrict__ pts,
                      const float* __restrict__ origin,
                      float* __restrict__ out)
{
    __shared__ int    s_cnt;
    __shared__ short  s_list[NP];
    __shared__ int4   s_box[BATCH];
    __shared__ float4 s_q0[BATCH];
    __shared__ float4 s_q1[BATCH];
    __shared__ float2 s_q2[BATCH];
    __shared__ float4 s_sem[BATCH][4];
    __shared__ float  s_red[HALF][2 * NC + 1];   // half-1 partial accumulators

    const int t = threadIdx.x;
    if (t == 0) s_cnt = 0;
    __syncthreads();

    const int tlo_x = blockIdx.x * TX;
    const int tlo_y = blockIdx.y * TY;
    const int tlo_z = blockIdx.z * TZ;
    const int thi_x = tlo_x + TX - 1;
    const int thi_y = min(tlo_y + TY - 1, WW - 1);
    const int thi_z = min(tlo_z + TZ - 1, DDZ - 1);

    // Cooperative coarse cull (all 256 threads)
    for (int g = t; g < NP; g += TPB) {
        int4 bx = g_box[g];
        bool hit = (bx.x - bx.w <= thi_x) && (bx.x + bx.w >= tlo_x)
                && (bx.y - bx.w <= thi_y) && (bx.y + bx.w >= tlo_y)
                && (bx.z - bx.w <= thi_z) && (bx.z + bx.w >= tlo_z);
        if (hit) {
            int pos = atomicAdd(&s_cnt, 1);
            s_list[pos] = (short)g;
        }
    }
    __syncthreads();
    const int nlist = s_cnt;

    // Two halves: warps 0-3 = half 0 (even survivors), warps 4-7 = half 1 (odd)
    const int half = t >> 7;         // 0 or 1
    const int tl   = t & (HALF - 1);

    // Thread -> voxel pair (same map for both halves)
    const int tz = tl & (TZS - 1);
    const int ty = (tl >> 2) & (TY - 1);
    const int tx = tl >> 5;
    const int x  = tlo_x + tx;
    const int y  = tlo_y + ty;
    const int z0 = tlo_z + tz;
    const int z1 = z0 + TZS;
    const bool valid0 = (y < WW);
    const bool valid1 = valid0 && (z1 < DDZ);

    const int pidx0 = (x * WW + y) * DDZ + z0;
    const int pidx1 = pidx0 + TZS;

    float px = 0.f, py = 0.f, pz0 = 0.f, pz1 = 0.f;
    int pix = -100000, piy = -100000, piz0 = -100000, piz1 = -100000;
    if (valid0) {
        px  = pts[pidx0 * 3 + 0];
        py  = pts[pidx0 * 3 + 1];
        pz0 = pts[pidx0 * 3 + 2];
        float ox = origin[0], oy = origin[1], oz = origin[2];
        pix  = (int)((px - ox) / GRID_SZ);
        piy  = (int)((py - oy) / GRID_SZ);
        piz0 = (int)((pz0 - oz) / GRID_SZ);
        if (valid1) {
            pz1  = pts[pidx1 * 3 + 2];
            piz1 = (int)((pz1 - origin[2]) / GRID_SZ);
        }
    }

    float acc0[NC], acc1[NC];
#pragma unroll
    for (int c = 0; c < NC; c++) { acc0[c] = 0.0f; acc1[c] = 0.0f; }

    for (int base = 0; base < nlist; base += BATCH) {
        const int cnt = min(BATCH, nlist - base);

        if (t < cnt) {
            int g = s_list[base + t];
            s_box[t] = g_box[g];
            s_q0[t]  = g_q0[g];
            s_q1[t]  = g_q1[g];
            s_q2[t]  = g_q2[g];
#pragma unroll
            for (int q = 0; q < 4; q++) s_sem[t][q] = g_sem4[g][q];
        }
        __syncthreads();

        // Each half walks its own stride-2 subset of the staged batch
        for (int i = half; i < cnt; i += 2) {
            const int4 bx = s_box[i];
            bool ibxy = (abs(pix - bx.x) <= bx.w) & (abs(piy - bx.y) <= bx.w);
            bool ib0 = ibxy & (abs(piz0 - bx.z) <= bx.w);
            bool ib1 = ibxy & (abs(piz1 - bx.z) <= bx.w);
            if (__any_sync(0xffffffffu, ib0 | ib1)) {
                const float4 q1 = s_q1[i];
                const float2 q2 = s_q2[i];
                const float4 q0 = s_q0[i];
                float dx  = px  - q1.w;
                float dy  = py  - q2.x;
                float dz0 = pz0 - q2.y;
                float dz1 = pz1 - q2.y;
                float exy = fmaf(q0.x * dx, dx, fmaf(q0.y * dy, dy, q1.x * dx * dy));
                float h   = fmaf(q1.y, dy, q1.z * dx);
                float e0  = fmaf(fmaf(q0.z, dz0, h), dz0, exy);
                float e1  = fmaf(fmaf(q0.z, dz1, h), dz1, exy);
                float w0 = ib0 ? __expf(e0) : 0.0f;
                float w1 = ib1 ? __expf(e1) : 0.0f;
                const float4 sA = s_sem[i][0];
                const float4 sB = s_sem[i][1];
                const float4 sC = s_sem[i][2];
                const float4 sD = s_sem[i][3];
                acc0[0]  = fmaf(w0, sA.x, acc0[0]);   acc1[0]  = fmaf(w1, sA.x, acc1[0]);
                acc0[1]  = fmaf(w0, sA.y, acc0[1]);   acc1[1]  = fmaf(w1, sA.y, acc1[1]);
                acc0[2]  = fmaf(w0, sA.z, acc0[2]);   acc1[2]  = fmaf(w1, sA.z, acc1[2]);
                acc0[3]  = fmaf(w0, sA.w, acc0[3]);   acc1[3]  = fmaf(w1, sA.w, acc1[3]);
                acc0[4]  = fmaf(w0, sB.x, acc0[4]);   acc1[4]  = fmaf(w1, sB.x, acc1[4]);
                acc0[5]  = fmaf(w0, sB.y, acc0[5]);   acc1[5]  = fmaf(w1, sB.y, acc1[5]);
                acc0[6]  = fmaf(w0, sB.z, acc0[6]);   acc1[6]  = fmaf(w1, sB.z, acc1[6]);
                acc0[7]  = fmaf(w0, sB.w, acc0[7]);   acc1[7]  = fmaf(w1, sB.w, acc1[7]);
                acc0[8]  = fmaf(w0, sC.x, acc0[8]);   acc1[8]  = fmaf(w1, sC.x, acc1[8]);
                acc0[9]  = fmaf(w0, sC.y, acc0[9]);   acc1[9]  = fmaf(w1, sC.y, acc1[9]);
                acc0[10] = fmaf(w0, sC.z, acc0[10]);  acc1[10] = fmaf(w1, sC.z, acc1[10]);
                acc0[11] = fmaf(w0, sC.w, acc0[11]);  acc1[11] = fmaf(w1, sC.w, acc1[11]);
                acc0[12] = fmaf(w0, sD.x, acc0[12]);  acc1[12] = fmaf(w1, sD.x, acc1[12]);
            }
        }
        __syncthreads();
    }

    // Merge half-1 partials into half-0 and store
    if (half == 1) {
#pragma unroll
        for (int c = 0; c < NC; c++) {
            s_red[tl][c]      = acc0[c];
            s_red[tl][NC + c] = acc1[c];
        }
    }
    __syncthreads();
    if (half == 0) {
        if (valid0) {
#pragma unroll
            for (int c = 0; c < NC; c++)
                out[pidx0 * NC + c] = acc0[c] + s_red[tl][c];
        }
        if (valid1) {
#pragma unroll
            for (int c = 0; c < NC; c++)
                out[pidx1 * NC + c] = acc1[c] + s_red[tl][NC + c];
        }
    }
}

extern "C" void kernel_launch(void* const* d_in, const int* in_sizes, int n_in,
                              void* d_out, int out_size)
{
    const float* pts      = (const float*)d_in[0];   // [1,129600,3]
    const float* means3D  = (const float*)d_in[1];   // [1,2048,3]
    const float* opac     = (const float*)d_in[2];   // [1,2048]
    const float* sem      = (const float*)d_in[3];   // [1,2048,13]
    const float* scales   = (const float*)d_in[4];   // [1,2048,3]
    const float* cov3D    = (const float*)d_in[5];   // [1,2048,3,3]
    const float* origin   = (const float*)d_in[6];   // [3]
    float* out = (float*)d_out;                      // [129600,13] f32

    precompute_kernel<<<(NP + 255) / 256, 256>>>(means3D, opac, sem, scales, cov3D, origin);

    dim3 grid(HH / TX, (WW + TY - 1) / TY, (DDZ + TZ - 1) / TZ); // 15, 8, 5
    aggregate_kernel<<<grid, TPB>>>(pts, origin, out);
}